// round 2
// baseline (speedup 1.0000x reference)
#include <cuda_runtime.h>

// ---------------------------------------------------------------------------
// NeuralSplineFlow3D fused kernel (fp32, FFMA2-packed, smem-resident weights)
// ---------------------------------------------------------------------------

#define THREADS   256
#define PW        68          // smem pitch (floats) for 64-wide hidden weights
#define PO        80          // smem pitch (floats) for output weights (2x37 + pad)
#define TBc       5.0f
#define MINc      0.001f
#define LOGZc     (-2.7568155996140194f)   // -1.5*log(2*pi)
#define DCONSTf   (0.5397424697f)          // log(exp(1-0.001)-1)

// smem layout (float offsets)
#define SM_WT     0                         // 4*64*68 = 17408
#define SM_WO     (SM_WT + 4*64*PW)         // 64*80   = 5120
#define SM_WIN    (SM_WO + 64*PO)           // 64
#define SM_BIN    (SM_WIN + 64)             // 64
#define SM_BBLK   (SM_BIN + 64)             // 256
#define SM_BOUT   (SM_BBLK + 256)           // 80
#define SM_H      (SM_BOUT + PO)            // 64*256 = 16384
#define SM_T      (SM_H + 64*256)           // 64*256 = 16384
#define SM_TOTALF (SM_T + 64*256)
#define SMEM_BYTES (SM_TOTALF * 4)          // 223040 bytes

typedef unsigned long long u64;

static __device__ __forceinline__ u64 ffma2(u64 a, u64 b, u64 c) {
    u64 d;
    asm("fma.rn.f32x2 %0, %1, %2, %3;" : "=l"(d) : "l"(a), "l"(b), "l"(c));
    return d;
}
static __device__ __forceinline__ u64 pk2(float v) {
    u64 r;
    asm("mov.b64 %0, {%1, %1};" : "=l"(r) : "f"(v));
    return r;
}
static __device__ __forceinline__ void upk2(u64 v, float& lo, float& hi) {
    asm("mov.b64 {%0, %1}, %2;" : "=f"(lo), "=f"(hi) : "l"(v));
}

static __device__ __forceinline__ float softplusf(float x) {
    // log1p(exp(x)), overflow-stable
    return fmaxf(x, 0.0f) + log1pf(__expf(-fabsf(x)));
}

// dst[o][tid] = bias[o] + sum_k act(in[k][tid]) * Wt[k][o]; optional += into dst.
// Wt row pitch PW (16B aligned). Activation panels are per-thread columns, no sync.
template<bool RELU, bool ADD>
static __device__ __forceinline__ void dense64(const float* __restrict__ Wt,
                                               const float* __restrict__ bias,
                                               const float* __restrict__ inb,
                                               float* __restrict__ dst, int tid) {
    u64 acc[32];
#pragma unroll
    for (int q = 0; q < 32; ++q)
        acc[q] = *reinterpret_cast<const u64*>(bias + 2 * q);
#pragma unroll 1
    for (int k = 0; k < 64; ++k) {
        float r = inb[(k << 8) + tid];
        if (RELU) r = fmaxf(r, 0.0f);
        u64 rr = pk2(r);
        const float* wr = Wt + k * PW;
#pragma unroll
        for (int q = 0; q < 16; ++q) {
            ulonglong2 w = *reinterpret_cast<const ulonglong2*>(wr + 4 * q);
            acc[2 * q]     = ffma2(rr, w.x, acc[2 * q]);
            acc[2 * q + 1] = ffma2(rr, w.y, acc[2 * q + 1]);
        }
    }
#pragma unroll
    for (int q = 0; q < 32; ++q) {
        float lo, hi;
        upk2(acc[q], lo, hi);
        if (ADD) {
            dst[((2 * q) << 8) + tid]     += lo;
            dst[((2 * q + 1) << 8) + tid] += hi;
        } else {
            dst[((2 * q) << 8) + tid]     = lo;
            dst[((2 * q + 1) << 8) + tid] = hi;
        }
    }
}

// 37 outputs (one spline dim) into registers p[0..36]. No relu on input.
static __device__ __forceinline__ void denseOutHalf(const float* __restrict__ Wo,
                                                    const float* __restrict__ bias,
                                                    const float* __restrict__ inb,
                                                    int tid, float* __restrict__ p) {
    u64 acc[18];
    float accs;
#pragma unroll
    for (int q = 0; q < 18; ++q)
        acc[q] = *reinterpret_cast<const u64*>(bias + 2 * q);
    accs = bias[36];
#pragma unroll 1
    for (int k = 0; k < 64; ++k) {
        float r = inb[(k << 8) + tid];
        u64 rr = pk2(r);
        const float* wr = Wo + k * PO;
#pragma unroll
        for (int q = 0; q < 9; ++q) {
            ulonglong2 w = *reinterpret_cast<const ulonglong2*>(wr + 4 * q);
            acc[2 * q]     = ffma2(rr, w.x, acc[2 * q]);
            acc[2 * q + 1] = ffma2(rr, w.y, acc[2 * q + 1]);
        }
        accs = fmaf(r, wr[36], accs);
    }
#pragma unroll
    for (int q = 0; q < 18; ++q) upk2(acc[q], p[2 * q], p[2 * q + 1]);
    p[36] = accs;
}

// softmax(12 logits at p[B..B+11]) -> bin sizes; optional bin search for xc;
// outputs left knot and bin size for `bin`. Fully unrolled, register-resident.
template<int B, bool CB>
static __device__ __forceinline__ void soft_knots(const float* __restrict__ p, float xc,
                                                  int& bin, float& left, float& sz) {
    float e[12];
    float m = p[B];
#pragma unroll
    for (int j = 1; j < 12; ++j) m = fmaxf(m, p[B + j]);
    float s = 0.0f;
#pragma unroll
    for (int j = 0; j < 12; ++j) { e[j] = __expf(p[B + j] - m); s += e[j]; }
    float cinv = 0.988f * __fdividef(1.0f, s);       // (1 - NB*min)/sum
#pragma unroll
    for (int j = 0; j < 12; ++j) e[j] = fmaf(e[j], cinv, MINc);

    if (CB) {
        bin = 0;
        float run = 0.0f;
#pragma unroll
        for (int j = 0; j < 12; ++j) {
            run += e[j];
            float ks = (j == 11) ? (TBc + 1e-6f) : fmaf(10.0f, run, -TBc);
            if (xc >= ks) ++bin;
        }
    }
    float run = 0.0f, prev = -TBc;
#pragma unroll
    for (int j = 0; j < 12; ++j) {
        run += e[j];
        float right = (j == 11) ? TBc : fmaf(10.0f, run, -TBc);
        if (j == bin) { left = prev; sz = right - prev; }
        prev = right;
    }
}

// Rational-quadratic spline; p: uw=p[0..11], uh=p[12..23], ud=p[24..36].
static __device__ __forceinline__ void rq_spline(const float* __restrict__ p, float xin,
                                                 float& yout, float& ladout) {
    bool inside = (xin >= -TBc) && (xin <= TBc);
    float xc = fminf(fmaxf(xin, -TBc), TBc);

    int bin = 0;
    float in_cw, in_w, in_ch, in_h;
    soft_knots<0,  true >(p, xc, bin, in_cw, in_w);   // widths (defines bin)
    soft_knots<12, false>(p, xc, bin, in_ch, in_h);   // heights (same bin)

    // d = MIND + softplus(ud_p);  ud_p = [DCONST, ud[0..12], DCONST]; bin in [0,11]
    float uk = DCONSTf, uk1 = DCONSTf;
#pragma unroll
    for (int j = 1; j <= 12; ++j) {
        float v = p[23 + j];            // ud[j-1]
        if (j == bin)     uk  = v;
        if (j == bin + 1) uk1 = v;
    }
    float dk  = MINc + softplusf(uk);
    float dk1 = MINc + softplusf(uk1);

    float invw  = __fdividef(1.0f, in_w);
    float delta = in_h * invw;
    float theta = (xc - in_cw) * invw;
    float om    = 1.0f - theta;
    float t1m   = theta * om;
    float th2   = theta * theta;
    float num   = in_h * (delta * th2 + dk * t1m);
    float den   = delta + (dk + dk1 - 2.0f * delta) * t1m;
    float y     = in_ch + __fdividef(num, den);
    float dnum  = (delta * delta) * (dk1 * th2 + 2.0f * delta * t1m + dk * om * om);
    float lad   = __logf(dnum) - 2.0f * __logf(den);

    yout   = inside ? y : xin;
    ladout = inside ? lad : 0.0f;
}

extern "C" __global__ void __launch_bounds__(THREADS, 1)
nsf_kernel(const float* __restrict__ x,
           const float* __restrict__ W_in,  const float* __restrict__ b_in,
           const float* __restrict__ W_blk, const float* __restrict__ b_blk,
           const float* __restrict__ W_out, const float* __restrict__ b_out,
           float* __restrict__ out, int n) {
    extern __shared__ float sm[];
    float* sWt  = sm + SM_WT;
    float* sWo  = sm + SM_WO;
    float* sWin = sm + SM_WIN;
    float* sbin = sm + SM_BIN;
    float* sbb  = sm + SM_BBLK;
    float* sbo  = sm + SM_BOUT;
    float* sh   = sm + SM_H;
    float* st   = sm + SM_T;

    const int tid  = threadIdx.x;
    const int gid  = blockIdx.x * THREADS + tid;
    const bool valid = (gid < n);
    const int g    = valid ? gid : (n - 1);

    float z0 = x[3 * g + 0];
    float z1 = x[3 * g + 1];
    float z2 = x[3 * g + 2];
    float lad_total = 0.0f;

    for (int it = 0; it < 8; ++it) {
        __syncthreads();   // previous transform done reading weights

        // ---- stage this transform's weights into smem (coalesced gmem reads) ----
        const float* gW = W_blk + it * 16384;
        for (int idx = tid; idx < 16384; idx += THREADS) {
            int l = idx >> 12, rem = idx & 4095, o = rem >> 6, k = rem & 63;
            sWt[(l * 64 + k) * PW + o] = gW[idx];
        }
        const float* gWo = W_out + it * 74 * 64;
        for (int idx = tid; idx < 74 * 64; idx += THREADS) {
            int o = idx >> 6, k = idx & 63;
            int col = (o < 37) ? o : (o + 3);
            sWo[k * PO + col] = gWo[idx];
        }
        if (tid < 64) {
            sWin[tid] = W_in[it * 64 + tid];
            sbin[tid] = b_in[it * 64 + tid];
        }
        sbb[tid] = b_blk[it * 256 + tid];
        if (tid < 74) {
            int col = (tid < 37) ? tid : (tid + 3);
            sbo[col] = b_out[it * 74 + tid];
        }
        __syncthreads();

        // ---- per-transform: reverse z, split ident/tr ----
        float c = z2, t0 = z1, t1 = z0;

        // h = ident * W_in + b_in
#pragma unroll 8
        for (int o = 0; o < 64; ++o)
            sh[(o << 8) + tid] = fmaf(c, sWin[o], sbin[o]);

        // two residual blocks
        dense64<true, false>(sWt,               sbb,       sh, st, tid);
        dense64<true, true >(sWt +  64 * PW,    sbb +  64, st, sh, tid);
        dense64<true, false>(sWt + 128 * PW,    sbb + 128, sh, st, tid);
        dense64<true, true >(sWt + 192 * PW,    sbb + 192, st, sh, tid);

        // output params + splines (one dim at a time to bound register pressure)
        float y0, l0, y1, l1;
        {
            float p[37];
            denseOutHalf(sWo,      sbo,      sh, tid, p);
            rq_spline(p, t0, y0, l0);
        }
        {
            float p[37];
            denseOutHalf(sWo + 40, sbo + 40, sh, tid, p);
            rq_spline(p, t1, y1, l1);
        }

        z0 = c; z1 = y0; z2 = y1;
        lad_total += l0 + l1;
    }

    if (valid)
        out[gid] = fmaf(-0.5f, z0 * z0 + z1 * z1 + z2 * z2, LOGZc + lad_total);
}

extern "C" void kernel_launch(void* const* d_in, const int* in_sizes, int n_in,
                              void* d_out, int out_size) {
    const float* x     = (const float*)d_in[0];
    const float* W_in  = (const float*)d_in[1];
    const float* b_in  = (const float*)d_in[2];
    const float* W_blk = (const float*)d_in[3];
    const float* b_blk = (const float*)d_in[4];
    const float* W_out = (const float*)d_in[5];
    const float* b_out = (const float*)d_in[6];
    float* out = (float*)d_out;

    int n = in_sizes[0] / 3;
    cudaFuncSetAttribute(nsf_kernel, cudaFuncAttributeMaxDynamicSharedMemorySize,
                         SMEM_BYTES);
    int blocks = (n + THREADS - 1) / THREADS;
    nsf_kernel<<<blocks, THREADS, SMEM_BYTES>>>(x, W_in, b_in, W_blk, b_blk,
                                                W_out, b_out, out, n);
}